// round 16
// baseline (speedup 1.0000x reference)
#include <cuda_runtime.h>
#include <cuda_fp16.h>
#include <cstdint>

// Problem constants
constexpr int Bx    = 2;
constexpr int Nx    = 2048;
constexpr int Dx    = 768;
constexpr int Hx    = 12;
constexpr int DHx   = 64;
constexpr int INNER = Hx * DHx;        // 768
constexpr int TRI   = 3 * INNER;       // 2304
constexpr int OUTD  = 768;
constexpr int MROWS = Bx * Nx;         // 4096

// Scratch (fp16)
__device__ __half g_qkvh[(size_t)MROWS * TRI];
__device__ __half g_atth[(size_t)MROWS * INNER];
__device__ __half g_xh  [(size_t)MROWS * Dx];
__device__ __half g_wqh [(size_t)Dx * TRI];      // w_qkv fp16 (same layout)
__device__ __half g_woh [(size_t)INNER * OUTD];  // w_out fp16 (same layout)

// ---------------------------------------------------------------------------
// helpers
// ---------------------------------------------------------------------------
__device__ __forceinline__ unsigned pack2(float lo, float hi) {
    __half2 h = __floats2half2_rn(lo, hi);
    return *(unsigned*)&h;
}
__device__ __forceinline__ unsigned ex2_h2(unsigned h2) {
    unsigned r;
    asm("ex2.approx.f16x2 %0, %1;" : "=r"(r) : "r"(h2));
    return r;
}
__device__ __forceinline__ void redg_f32(float* p, float v) {
    asm volatile("red.global.add.f32 [%0], %1;" :: "l"(p), "f"(v) : "memory");
}
// fp32-accumulator MMA
__device__ __forceinline__ void mma_f16(float* c,
    unsigned a0, unsigned a1, unsigned a2, unsigned a3,
    unsigned b0, unsigned b1)
{
    asm volatile(
        "mma.sync.aligned.m16n8k16.row.col.f32.f16.f16.f32 "
        "{%0,%1,%2,%3}, {%4,%5,%6,%7}, {%8,%9}, {%0,%1,%2,%3};\n"
        : "+f"(c[0]), "+f"(c[1]), "+f"(c[2]), "+f"(c[3])
        : "r"(a0), "r"(a1), "r"(a2), "r"(a3), "r"(b0), "r"(b1));
}
// fp16-accumulator MMA (C layout == packed A-fragment layout)
__device__ __forceinline__ void mma_f16h(unsigned* c,
    unsigned a0, unsigned a1, unsigned a2, unsigned a3,
    unsigned b0, unsigned b1)
{
    asm volatile(
        "mma.sync.aligned.m16n8k16.row.col.f16.f16.f16.f16 "
        "{%0,%1}, {%2,%3,%4,%5}, {%6,%7}, {%0,%1};\n"
        : "+r"(c[0]), "+r"(c[1])
        : "r"(a0), "r"(a1), "r"(a2), "r"(a3), "r"(b0), "r"(b1));
}
__device__ __forceinline__ void ldsm4(unsigned& r0, unsigned& r1,
                                      unsigned& r2, unsigned& r3, unsigned addr)
{
    asm volatile("ldmatrix.sync.aligned.m8n8.x4.shared.b16 {%0,%1,%2,%3}, [%4];"
        : "=r"(r0), "=r"(r1), "=r"(r2), "=r"(r3) : "r"(addr));
}
__device__ __forceinline__ void ldsm4t(unsigned& r0, unsigned& r1,
                                       unsigned& r2, unsigned& r3, unsigned addr)
{
    asm volatile("ldmatrix.sync.aligned.m8n8.x4.trans.shared.b16 {%0,%1,%2,%3}, [%4];"
        : "=r"(r0), "=r"(r1), "=r"(r2), "=r"(r3) : "r"(addr));
}
__device__ __forceinline__ void cp_async16(unsigned smem_dst, const void* gptr) {
    asm volatile("cp.async.cg.shared.global [%0], [%1], 16;\n" :: "r"(smem_dst), "l"(gptr));
}
__device__ __forceinline__ void cp_commit() {
    asm volatile("cp.async.commit_group;\n");
}
template<int Ngr> __device__ __forceinline__ void cp_wait() {
    asm volatile("cp.async.wait_group %0;\n" :: "n"(Ngr));
}
__device__ __forceinline__ unsigned smem_u32(const void* p) {
    return (unsigned)__cvta_generic_to_shared(p);
}

// ---------------------------------------------------------------------------
// fused prologue: fp32->fp16 cvt of x, w_qkv, w_out  +  bias-init of d_out
// ---------------------------------------------------------------------------
__global__ __launch_bounds__(256) void cvt4_kernel(
    const float4* __restrict__ s0, uint2* __restrict__ d0, int n0,
    const float4* __restrict__ s1, uint2* __restrict__ d1, int n1,
    const float4* __restrict__ s2, uint2* __restrict__ d2, int n2,
    const float4* __restrict__ bias_out, float4* __restrict__ outi, int n3)
{
    int i = blockIdx.x * blockDim.x + threadIdx.x;
    if (i < n0) {
        float4 v = s0[i];
        d0[i] = make_uint2(pack2(v.x, v.y), pack2(v.z, v.w));
    } else if (i < n0 + n1) {
        int j = i - n0;
        float4 v = s1[j];
        d1[j] = make_uint2(pack2(v.x, v.y), pack2(v.z, v.w));
    } else if (i < n0 + n1 + n2) {
        int j = i - n0 - n1;
        float4 v = s2[j];
        d2[j] = make_uint2(pack2(v.x, v.y), pack2(v.z, v.w));
    } else if (i < n0 + n1 + n2 + n3) {
        int j = i - n0 - n1 - n2;
        outi[j] = bias_out[j & (OUTD / 4 - 1)];    // OUTD/4 = 192... not pow2
    }
}
// (OUTD/4 = 192 is not a power of two; use modulo instead)
__global__ __launch_bounds__(256) void init_out_kernel(
    const float4* __restrict__ bias_out, float4* __restrict__ outi, int n)
{
    int i = blockIdx.x * blockDim.x + threadIdx.x;
    if (i < n) outi[i] = bias_out[i % (OUTD / 4)];
}

// ---------------------------------------------------------------------------
// fp16 GEMM: C[M,Nn] (+)= A[M,K_eff]@B[K_eff,Nn] (+ bias)   (B untransposed)
// MT = 16-row m-subtiles per warp.  CTA tile = (MT*32) x 128, 4 warps,
// BK=64, cp.async double buffer, ldmatrix(+trans for B).
// blockIdx.z selects a K-split chunk of size Ksp.
// mode 1: store fp16 with bias, scale cols < INNER by QSCALE.
// mode 2: red.global.add.f32 partials (bias pre-initialized in C).
// ---------------------------------------------------------------------------
constexpr float QSCALE = 0.125f * 1.4426950408889634f;
constexpr int GROWB = 144;                 // A smem row bytes (64 halves + pad)
constexpr int BROWB = 272;                 // B smem row bytes (128 halves + pad)
constexpr int BBUF  = 64 * BROWB;          // 17408 B per B buffer
template<int MT> constexpr int abuf()     { return MT * 32 * GROWB; }
template<int MT> constexpr int gemm_smem(){ return 2 * abuf<MT>() + 2 * BBUF; }

template<int MT, int MAXB>
__global__ __launch_bounds__(128, MAXB) void gemm_f16_kernel(
    const __half* __restrict__ A, const __half* __restrict__ Bm,
    const float* __restrict__ bias, void* __restrict__ Cv,
    int Kfull, int Ksp, int Nn, int mode)
{
    extern __shared__ __align__(128) unsigned char smraw[];
    const unsigned sbase = smem_u32(smraw);
    constexpr int ABUF = MT * 32 * GROWB;

    const int tid  = threadIdx.x;
    const int lane = tid & 31;
    const int warp = tid >> 5;
    const int wm   = warp >> 1;            // 0..1
    const int wn   = warp & 1;             // 0..1
    const int g    = lane >> 2;
    const int cq   = lane & 3;
    const int m0   = blockIdx.y * (MT * 32);
    const int n0   = blockIdx.x * 128;
    const int koff = blockIdx.z * Ksp;
    const int nchunks = Ksp / 64;

    float acc[MT][8][4] = {};

    auto stage = [&](int slot, int k0) {
        // A: MT*32 rows x 64 halves
        #pragma unroll
        for (int i = 0; i < MT * 2; i++) {
            int idx = tid + i * 128;       // MT*256 chunks of 16B
            int row = idx >> 3;
            int j   = idx & 7;
            cp_async16(sbase + slot * ABUF + row * GROWB + j * 16,
                       A + (size_t)(m0 + row) * Kfull + koff + k0 + j * 8);
        }
        // B: 64 K-rows x 128 halves (untransposed w)
        #pragma unroll
        for (int i = 0; i < 8; i++) {
            int idx = tid + i * 128;       // 1024 chunks of 16B
            int row = idx >> 4;
            int j   = idx & 15;
            cp_async16(sbase + 2 * ABUF + slot * BBUF + row * BROWB + j * 16,
                       Bm + (size_t)(koff + k0 + row) * Nn + n0 + j * 8);
        }
    };

    stage(0, 0);  cp_commit();
    stage(1, 64); cp_commit();

    // ldmatrix lane-address components (trans loads use a_row/a_col too)
    const int a_row = (lane & 7) + ((lane & 8) ? 8 : 0);
    const int a_col = (lane & 16) ? 16 : 0;

    for (int i = 0; i < nchunks; i++) {
        const int b = i & 1;
        if (i + 2 < nchunks) cp_wait<1>(); else cp_wait<0>();
        __syncthreads();

        const unsigned sA = sbase + b * ABUF;
        const unsigned sB = sbase + 2 * ABUF + b * BBUF + wn * 128;
        #pragma unroll
        for (int kd = 0; kd < 4; kd++) {
            unsigned a[MT][4], bb[4][4];
            #pragma unroll
            for (int mt = 0; mt < MT; mt++)
                ldsm4(a[mt][0], a[mt][1], a[mt][2], a[mt][3],
                      sA + (wm * (MT * 16) + mt * 16 + a_row) * GROWB + kd * 32 + a_col);
            #pragma unroll
            for (int nb = 0; nb < 4; nb++)
                ldsm4t(bb[nb][0], bb[nb][1], bb[nb][2], bb[nb][3],
                       sB + (kd * 16 + a_row) * BROWB + nb * 32 + a_col);
            #pragma unroll
            for (int mt = 0; mt < MT; mt++)
                #pragma unroll
                for (int nt = 0; nt < 8; nt++)
                    mma_f16(acc[mt][nt], a[mt][0], a[mt][1], a[mt][2], a[mt][3],
                            bb[nt >> 1][(nt & 1) * 2], bb[nt >> 1][(nt & 1) * 2 + 1]);
        }
        __syncthreads();
        if (i + 2 < nchunks) { stage(b, (i + 2) * 64); cp_commit(); }
    }

    // Epilogue
    #pragma unroll
    for (int mt = 0; mt < MT; mt++) {
        int r0 = m0 + wm * (MT * 16) + mt * 16 + g;
        #pragma unroll
        for (int nt = 0; nt < 8; nt++) {
            int c = n0 + wn * 64 + nt * 8 + 2 * cq;
            if (mode == 1) {
                float2 b2 = *(const float2*)&bias[c];
                float sc = (c < INNER) ? QSCALE : 1.0f;   // pre-scale Q columns
                __half* C = (__half*)Cv;
                *(unsigned*)&C[(size_t)r0 * Nn + c] =
                    pack2((acc[mt][nt][0] + b2.x) * sc, (acc[mt][nt][1] + b2.y) * sc);
                *(unsigned*)&C[(size_t)(r0 + 8) * Nn + c] =
                    pack2((acc[mt][nt][2] + b2.x) * sc, (acc[mt][nt][3] + b2.y) * sc);
            } else {
                float* C = (float*)Cv;
                redg_f32(&C[(size_t)r0 * Nn + c],           acc[mt][nt][0]);
                redg_f32(&C[(size_t)r0 * Nn + c + 1],       acc[mt][nt][1]);
                redg_f32(&C[(size_t)(r0 + 8) * Nn + c],     acc[mt][nt][2]);
                redg_f32(&C[(size_t)(r0 + 8) * Nn + c + 1], acc[mt][nt][3]);
            }
        }
    }
}

// ---------------------------------------------------------------------------
// fp16 flash attention, unnormalized softmax (p = 2^s), l via tensor core
// (ones-column block in V smem), fp16-accumulator QK^T (S regs == packed P).
// CTA = (b,h,128 Q rows), 128 thr, 4 warps x 32 rows.
// ---------------------------------------------------------------------------
constexpr int AROWB = 176;                              // bytes/row (88 halves)
constexpr int QBUF  = 128 * AROWB;                      // 22528
constexpr int KVBUF = 64 * AROWB;                       // 11264
constexpr int ATT_SMEM = QBUF + 4 * KVBUF;              // 67584 B

__global__ __launch_bounds__(128, 3) void attn_f16_kernel(
    const __half* __restrict__ qkv, __half* __restrict__ outp)
{
    extern __shared__ __align__(128) unsigned char smraw[];
    const unsigned sbase = smem_u32(smraw);
    const unsigned sQ = sbase;
    const unsigned sK0 = sbase + QBUF;
    const unsigned sV0 = sbase + QBUF + 2 * KVBUF;

    const int tid  = threadIdx.x;
    const int lane = tid & 31;
    const int warp = tid >> 5;               // 0..3
    const int g    = lane >> 2;
    const int cq   = lane & 3;
    const int wr   = warp * 32;              // warp's 32-row base

    const int b  = blockIdx.z;
    const int h  = blockIdx.y;
    const int q0 = blockIdx.x * 128;

    const __half* qb = qkv + (size_t)(b * Nx + q0) * TRI + h * DHx;
    const __half* kb = qkv + (size_t)b * Nx * TRI + INNER + h * DHx;
    const __half* vb = qkv + (size_t)b * Nx * TRI + 2 * INNER + h * DHx;

    auto stage_kv = [&](int slot, int kt) {
        #pragma unroll
        for (int i = 0; i < 4; i++) {
            int idx = tid + i * 128;         // 512 chunks of 16B each for K and V
            int row = idx >> 3;
            int j   = idx & 7;
            cp_async16(sK0 + slot * KVBUF + row * AROWB + j * 16,
                       kb + (size_t)(kt + row) * TRI + j * 8);
            cp_async16(sV0 + slot * KVBUF + row * AROWB + j * 16,
                       vb + (size_t)(kt + row) * TRI + j * 8);
        }
    };

    // Prologue: Q + first two K/V tiles
    {
        #pragma unroll
        for (int i = 0; i < 8; i++) {
            int idx = tid + i * 128;         // 1024 chunks
            int row = idx >> 3;
            int j   = idx & 7;
            cp_async16(sQ + row * AROWB + j * 16,
                       qb + (size_t)row * TRI + j * 8);
        }
        stage_kv(0, 0);
        cp_commit();
        stage_kv(1, 64);
        cp_commit();
    }

    // Ones block: V cols 64-71 (bytes 128..143) of every row, both buffers.
    {
        int buf = tid >> 6;                  // 0..1
        int row = tid & 63;
        uint4 ones;
        ones.x = ones.y = ones.z = ones.w = 0x3C003C00u;   // fp16 1.0 pairs
        *(uint4*)(smraw + QBUF + 2 * KVBUF + buf * KVBUF + row * AROWB + 128) = ones;
    }

    cp_wait<1>();          // Q + KV tile0 complete
    __syncthreads();

    // ldmatrix lane-address components
    const int a_row = (lane & 7) + ((lane & 8) ? 8 : 0);
    const int a_col = (lane & 16) ? 16 : 0;
    const int b_row = (lane & 7) + ((lane & 16) ? 8 : 0);
    const int b_col = (lane & 8) ? 16 : 0;

    // Q fragment smem base addresses (fragments reloaded per tile)
    const unsigned qfa0 = sQ + (wr      + a_row) * AROWB + a_col;
    const unsigned qfa1 = sQ + (wr + 16 + a_row) * AROWB + a_col;

    float o[2][8][4] = {};
    float oL[2][4] = {};              // l accumulators (c[0]=row g, c[2]=row g+8)

    constexpr int NT = Nx / 64;       // 32 tiles
    for (int it = 0; it < NT; it++) {
        const int bf = it & 1;
        if (it + 2 < NT) cp_wait<1>(); else cp_wait<0>();
        __syncthreads();

        const unsigned sK = sK0 + bf * KVBUF;
        const unsigned sV = sV0 + bf * KVBUF;

        // S = Q @ K^T in fp16 accumulate (32 x 64 per warp)
        unsigned s[2][8][2] = {};     // fp16x2 accumulators == packed P layout
        #pragma unroll
        for (int kd = 0; kd < 4; kd++) {
            unsigned q0f[4], q1f[4], bk[4][4];
            ldsm4(q0f[0], q0f[1], q0f[2], q0f[3], qfa0 + kd * 32);
            ldsm4(q1f[0], q1f[1], q1f[2], q1f[3], qfa1 + kd * 32);
            #pragma unroll
            for (int p = 0; p < 4; p++)
                ldsm4(bk[p][0], bk[p][1], bk[p][2], bk[p][3],
                      sK + (p * 16 + b_row) * AROWB + kd * 32 + b_col);
            #pragma unroll
            for (int nt = 0; nt < 8; nt++) {
                mma_f16h(s[0][nt], q0f[0], q0f[1], q0f[2], q0f[3],
                         bk[nt >> 1][(nt & 1) * 2], bk[nt >> 1][(nt & 1) * 2 + 1]);
                mma_f16h(s[1][nt], q1f[0], q1f[1], q1f[2], q1f[3],
                         bk[nt >> 1][(nt & 1) * 2], bk[nt >> 1][(nt & 1) * 2 + 1]);
            }
        }

        // p = 2^s directly on packed fp16x2 accumulators
        unsigned ph2[2][8][2];
        #pragma unroll
        for (int mt = 0; mt < 2; mt++)
            #pragma unroll
            for (int nt = 0; nt < 8; nt++) {
                ph2[mt][nt][0] = ex2_h2(s[mt][nt][0]);   // row g
                ph2[mt][nt][1] = ex2_h2(s[mt][nt][1]);   // row g+8
            }

        // O += P @ V, and l += P @ ones
        #pragma unroll
        for (int kc = 0; kc < 4; kc++) {
            unsigned bv[4][4], be[4];
            #pragma unroll
            for (int p = 0; p < 4; p++)
                ldsm4t(bv[p][0], bv[p][1], bv[p][2], bv[p][3],
                       sV + (kc * 16 + a_row) * AROWB + p * 32 + a_col);
            ldsm4t(be[0], be[1], be[2], be[3],
                   sV + (kc * 16 + a_row) * AROWB + 128 + a_col);
            #pragma unroll
            for (int mt = 0; mt < 2; mt++) {
                unsigned pa0 = ph2[mt][2 * kc    ][0];
                unsigned pa1 = ph2[mt][2 * kc    ][1];
                unsigned pa2 = ph2[mt][2 * kc + 1][0];
                unsigned pa3 = ph2[mt][2 * kc + 1][1];
                #pragma unroll
                for (int nt = 0; nt < 8; nt++)
                    mma_f16(o[mt][nt], pa0, pa1, pa2, pa3,
                            bv[nt >> 1][(nt & 1) * 2], bv[nt >> 1][(nt & 1) * 2 + 1]);
                mma_f16(oL[mt], pa0, pa1, pa2, pa3, be[0], be[1]);
            }
        }
        __syncthreads();
        if (it + 2 < NT) { stage_kv(bf, (it + 2) * 64); cp_commit(); }
    }

    // Epilogue: l fully reduced in oL (c[0]=row g, c[2]=row g+8)
    const size_t obase = (size_t)(b * Nx + q0) * INNER + h * DHx;
    #pragma unroll
    for (int mt = 0; mt < 2; mt++) {
        float inv0 = 1.0f / oL[mt][0];
        float inv1 = 1.0f / oL[mt][2];
        int row = wr + mt * 16;
        #pragma unroll
        for (int nt = 0; nt < 8; nt++) {
            int c = nt * 8 + 2 * cq;
            *(unsigned*)&outp[obase + (size_t)(row + g    ) * INNER + c] =
                pack2(o[mt][nt][0] * inv0, o[mt][nt][1] * inv0);
            *(unsigned*)&outp[obase + (size_t)(row + g + 8) * INNER + c] =
                pack2(o[mt][nt][2] * inv1, o[mt][nt][3] * inv1);
        }
    }
}

// ---------------------------------------------------------------------------
extern "C" void kernel_launch(void* const* d_in, const int* in_sizes, int n_in,
                              void* d_out, int out_size)
{
    const float* x     = (const float*)d_in[0];
    const float* w_qkv = (const float*)d_in[1];
    const float* b_qkv = (const float*)d_in[2];
    const float* w_out = (const float*)d_in[3];
    const float* b_out = (const float*)d_in[4];
    float* out = (float*)d_out;

    __half *qkvh, *atth, *xh, *wqh, *woh;
    cudaGetSymbolAddress((void**)&qkvh, g_qkvh);
    cudaGetSymbolAddress((void**)&atth, g_atth);
    cudaGetSymbolAddress((void**)&xh,  g_xh);
    cudaGetSymbolAddress((void**)&wqh, g_wqh);
    cudaGetSymbolAddress((void**)&woh, g_woh);

    cudaFuncSetAttribute(gemm_f16_kernel<2, 4>,
                         cudaFuncAttributeMaxDynamicSharedMemorySize, gemm_smem<2>());
    cudaFuncSetAttribute(attn_f16_kernel,
                         cudaFuncAttributeMaxDynamicSharedMemorySize, ATT_SMEM);

    // 0a) fused fp32 -> fp16 conversion (x, w_qkv, w_out)
    {
        int n0 = MROWS * Dx / 4;       // 786432
        int n1 = Dx * TRI / 4;         // 442368
        int n2 = INNER * OUTD / 4;     // 147456
        int tot = n0 + n1 + n2;
        cvt4_kernel<<<(tot + 255) / 256, 256>>>(
            (const float4*)x,     (uint2*)xh,  n0,
            (const float4*)w_qkv, (uint2*)wqh, n1,
            (const float4*)w_out, (uint2*)woh, n2,
            nullptr, nullptr, 0);
    }
    // 0b) init d_out = bias (for split-K red.add)
    {
        int n3 = MROWS * OUTD / 4;     // 786432
        init_out_kernel<<<(n3 + 255) / 256, 256>>>(
            (const float4*)b_out, (float4*)out, n3);
    }
    // 1) QKV projection: CTA 64x128, grid 1152, no K split
    {
        dim3 grid(TRI / 128, MROWS / 64, 1);
        gemm_f16_kernel<2, 4><<<grid, 128, gemm_smem<2>()>>>(
            xh, wqh, b_qkv, qkvh, Dx, Dx, TRI, 1);
    }
    // 2) Attention (fp16 out)
    {
        dim3 grid(Nx / 128, Hx, Bx);
        attn_f16_kernel<<<grid, 128, ATT_SMEM>>>(qkvh, atth);
    }
    // 3) Output projection: split-K x2, red.global.add into bias-initialized out
    {
        dim3 grid(OUTD / 128, MROWS / 64, 2);
        gemm_f16_kernel<2, 4><<<grid, 128, gemm_smem<2>()>>>(
            atth, woh, nullptr, out, INNER, INNER / 2, OUTD, 2);
    }
}

// round 17
// speedup vs baseline: 1.0693x; 1.0693x over previous
#include <cuda_runtime.h>
#include <cuda_fp16.h>
#include <cstdint>

// Problem constants
constexpr int Bx    = 2;
constexpr int Nx    = 2048;
constexpr int Dx    = 768;
constexpr int Hx    = 12;
constexpr int DHx   = 64;
constexpr int INNER = Hx * DHx;        // 768
constexpr int TRI   = 3 * INNER;       // 2304
constexpr int OUTD  = 768;
constexpr int MROWS = Bx * Nx;         // 4096

// Scratch (fp16)
__device__ __half g_qkvh[(size_t)MROWS * TRI];
__device__ __half g_atth[(size_t)MROWS * INNER];
__device__ __half g_xh  [(size_t)MROWS * Dx];
__device__ __half g_wqh [(size_t)Dx * TRI];      // w_qkv fp16 (same layout)
__device__ __half g_woh [(size_t)INNER * OUTD];  // w_out fp16 (same layout)

// ---------------------------------------------------------------------------
// helpers
// ---------------------------------------------------------------------------
__device__ __forceinline__ unsigned pack2(float lo, float hi) {
    __half2 h = __floats2half2_rn(lo, hi);
    return *(unsigned*)&h;
}
__device__ __forceinline__ unsigned ex2_h2(unsigned h2) {
    unsigned r;
    asm("ex2.approx.f16x2 %0, %1;" : "=r"(r) : "r"(h2));
    return r;
}
// fp32-accumulator MMA
__device__ __forceinline__ void mma_f16(float* c,
    unsigned a0, unsigned a1, unsigned a2, unsigned a3,
    unsigned b0, unsigned b1)
{
    asm volatile(
        "mma.sync.aligned.m16n8k16.row.col.f32.f16.f16.f32 "
        "{%0,%1,%2,%3}, {%4,%5,%6,%7}, {%8,%9}, {%0,%1,%2,%3};\n"
        : "+f"(c[0]), "+f"(c[1]), "+f"(c[2]), "+f"(c[3])
        : "r"(a0), "r"(a1), "r"(a2), "r"(a3), "r"(b0), "r"(b1));
}
// fp16-accumulator MMA (C layout == packed A-fragment layout)
__device__ __forceinline__ void mma_f16h(unsigned* c,
    unsigned a0, unsigned a1, unsigned a2, unsigned a3,
    unsigned b0, unsigned b1)
{
    asm volatile(
        "mma.sync.aligned.m16n8k16.row.col.f16.f16.f16.f16 "
        "{%0,%1}, {%2,%3,%4,%5}, {%6,%7}, {%0,%1};\n"
        : "+r"(c[0]), "+r"(c[1])
        : "r"(a0), "r"(a1), "r"(a2), "r"(a3), "r"(b0), "r"(b1));
}
__device__ __forceinline__ void ldsm4(unsigned& r0, unsigned& r1,
                                      unsigned& r2, unsigned& r3, unsigned addr)
{
    asm volatile("ldmatrix.sync.aligned.m8n8.x4.shared.b16 {%0,%1,%2,%3}, [%4];"
        : "=r"(r0), "=r"(r1), "=r"(r2), "=r"(r3) : "r"(addr));
}
__device__ __forceinline__ void ldsm4t(unsigned& r0, unsigned& r1,
                                       unsigned& r2, unsigned& r3, unsigned addr)
{
    asm volatile("ldmatrix.sync.aligned.m8n8.x4.trans.shared.b16 {%0,%1,%2,%3}, [%4];"
        : "=r"(r0), "=r"(r1), "=r"(r2), "=r"(r3) : "r"(addr));
}
__device__ __forceinline__ void cp_async16(unsigned smem_dst, const void* gptr) {
    asm volatile("cp.async.cg.shared.global [%0], [%1], 16;\n" :: "r"(smem_dst), "l"(gptr));
}
__device__ __forceinline__ void cp_commit() {
    asm volatile("cp.async.commit_group;\n");
}
template<int Ngr> __device__ __forceinline__ void cp_wait() {
    asm volatile("cp.async.wait_group %0;\n" :: "n"(Ngr));
}
__device__ __forceinline__ unsigned smem_u32(const void* p) {
    return (unsigned)__cvta_generic_to_shared(p);
}

// ---------------------------------------------------------------------------
// fused one-shot fp32 -> fp16 conversion for x, w_qkv, w_out
// ---------------------------------------------------------------------------
__global__ __launch_bounds__(256) void cvt3_kernel(
    const float4* __restrict__ s0, uint2* __restrict__ d0, int n0,
    const float4* __restrict__ s1, uint2* __restrict__ d1, int n1,
    const float4* __restrict__ s2, uint2* __restrict__ d2, int n2)
{
    int i = blockIdx.x * blockDim.x + threadIdx.x;
    const float4* s; uint2* d; int j;
    if (i < n0)            { s = s0; d = d0; j = i; }
    else if (i < n0 + n1)  { s = s1; d = d1; j = i - n0; }
    else if (i < n0 + n1 + n2) { s = s2; d = d2; j = i - n0 - n1; }
    else return;
    float4 v = s[j];
    d[j] = make_uint2(pack2(v.x, v.y), pack2(v.z, v.w));
}

// ---------------------------------------------------------------------------
// fp16 GEMM + bias: C[M,Nn] = A[M,K] @ B[K,Nn] + bias   (B untransposed)
// MT = 16-row m-subtiles per warp.  CTA tile = (MT*32) x 128, 4 warps,
// BK=64, cp.async double buffer, ldmatrix(+trans for B).
// mode 1: store fp16, scale cols < INNER by QSCALE; mode 0: plain fp32.
// ---------------------------------------------------------------------------
constexpr float QSCALE = 0.125f * 1.4426950408889634f;
constexpr int GROWB = 144;                 // A smem row bytes (64 halves + pad)
constexpr int BROWB = 272;                 // B smem row bytes (128 halves + pad)
constexpr int BBUF  = 64 * BROWB;          // 17408 B per B buffer
template<int MT> constexpr int abuf()     { return MT * 32 * GROWB; }
template<int MT> constexpr int gemm_smem(){ return 2 * abuf<MT>() + 2 * BBUF; }

template<int MT, int MAXB>
__global__ __launch_bounds__(128, MAXB) void gemm_f16_kernel(
    const __half* __restrict__ A, const __half* __restrict__ Bm,
    const float* __restrict__ bias, void* __restrict__ Cv,
    int K, int Nn, int mode)
{
    extern __shared__ __align__(128) unsigned char smraw[];
    const unsigned sbase = smem_u32(smraw);
    constexpr int ABUF = MT * 32 * GROWB;

    const int tid  = threadIdx.x;
    const int lane = tid & 31;
    const int warp = tid >> 5;
    const int wm   = warp >> 1;            // 0..1
    const int wn   = warp & 1;             // 0..1
    const int g    = lane >> 2;
    const int cq   = lane & 3;
    const int m0   = blockIdx.y * (MT * 32);
    const int n0   = blockIdx.x * 128;
    const int nchunks = K / 64;

    float acc[MT][8][4] = {};

    auto stage = [&](int slot, int k0) {
        // A: MT*32 rows x 64 halves
        #pragma unroll
        for (int i = 0; i < MT * 2; i++) {
            int idx = tid + i * 128;       // MT*256 chunks of 16B
            int row = idx >> 3;
            int j   = idx & 7;
            cp_async16(sbase + slot * ABUF + row * GROWB + j * 16,
                       A + (size_t)(m0 + row) * K + k0 + j * 8);
        }
        // B: 64 K-rows x 128 halves (untransposed w)
        #pragma unroll
        for (int i = 0; i < 8; i++) {
            int idx = tid + i * 128;       // 1024 chunks of 16B
            int row = idx >> 4;
            int j   = idx & 15;
            cp_async16(sbase + 2 * ABUF + slot * BBUF + row * BROWB + j * 16,
                       Bm + (size_t)(k0 + row) * Nn + n0 + j * 8);
        }
    };

    stage(0, 0);  cp_commit();
    stage(1, 64); cp_commit();

    // ldmatrix lane-address components (trans loads use a_row/a_col too)
    const int a_row = (lane & 7) + ((lane & 8) ? 8 : 0);
    const int a_col = (lane & 16) ? 16 : 0;

    for (int i = 0; i < nchunks; i++) {
        const int b = i & 1;
        if (i + 2 < nchunks) cp_wait<1>(); else cp_wait<0>();
        __syncthreads();

        const unsigned sA = sbase + b * ABUF;
        const unsigned sB = sbase + 2 * ABUF + b * BBUF + wn * 128;
        #pragma unroll
        for (int kd = 0; kd < 4; kd++) {
            unsigned a[MT][4], bb[4][4];
            #pragma unroll
            for (int mt = 0; mt < MT; mt++)
                ldsm4(a[mt][0], a[mt][1], a[mt][2], a[mt][3],
                      sA + (wm * (MT * 16) + mt * 16 + a_row) * GROWB + kd * 32 + a_col);
            #pragma unroll
            for (int nb = 0; nb < 4; nb++)
                ldsm4t(bb[nb][0], bb[nb][1], bb[nb][2], bb[nb][3],
                       sB + (kd * 16 + a_row) * BROWB + nb * 32 + a_col);
            #pragma unroll
            for (int mt = 0; mt < MT; mt++)
                #pragma unroll
                for (int nt = 0; nt < 8; nt++)
                    mma_f16(acc[mt][nt], a[mt][0], a[mt][1], a[mt][2], a[mt][3],
                            bb[nt >> 1][(nt & 1) * 2], bb[nt >> 1][(nt & 1) * 2 + 1]);
        }
        __syncthreads();
        if (i + 2 < nchunks) { stage(b, (i + 2) * 64); cp_commit(); }
    }

    // Epilogue
    #pragma unroll
    for (int mt = 0; mt < MT; mt++) {
        int r0 = m0 + wm * (MT * 16) + mt * 16 + g;
        #pragma unroll
        for (int nt = 0; nt < 8; nt++) {
            int c = n0 + wn * 64 + nt * 8 + 2 * cq;
            float2 b2 = *(const float2*)&bias[c];
            float v00 = acc[mt][nt][0] + b2.x;
            float v01 = acc[mt][nt][1] + b2.y;
            float v10 = acc[mt][nt][2] + b2.x;
            float v11 = acc[mt][nt][3] + b2.y;
            if (mode == 1) {
                float sc = (c < INNER) ? QSCALE : 1.0f;   // pre-scale Q columns
                __half* C = (__half*)Cv;
                *(unsigned*)&C[(size_t)r0 * Nn + c]       = pack2(v00 * sc, v01 * sc);
                *(unsigned*)&C[(size_t)(r0 + 8) * Nn + c] = pack2(v10 * sc, v11 * sc);
            } else {
                float* C = (float*)Cv;
                *(float2*)&C[(size_t)r0 * Nn + c]       = make_float2(v00, v01);
                *(float2*)&C[(size_t)(r0 + 8) * Nn + c] = make_float2(v10, v11);
            }
        }
    }
}

// ---------------------------------------------------------------------------
// fp16 flash attention, unnormalized softmax (p = 2^s), fp16-acc QK^T
// (S regs == packed P layout; ex2 applied IN PLACE).  l computed by the
// tensor core against a CONSTANT all-ones B fragment (0x3C003C00 in every
// lane) — no ones block in smem, no ldsm for it.
// CTA = (b,h,128 Q rows), 128 thr, 4 warps x 32 rows.
// ---------------------------------------------------------------------------
constexpr int AROWB = 144;                              // bytes/row (64 halves + pad)
constexpr int QBUF  = 128 * AROWB;                      // 18432
constexpr int KVBUF = 64 * AROWB;                       // 9216
constexpr int ATT_SMEM = QBUF + 4 * KVBUF;              // 55296 B

__global__ __launch_bounds__(128, 3) void attn_f16_kernel(
    const __half* __restrict__ qkv, __half* __restrict__ outp)
{
    extern __shared__ __align__(128) unsigned char smraw[];
    const unsigned sbase = smem_u32(smraw);
    const unsigned sQ = sbase;
    const unsigned sK0 = sbase + QBUF;
    const unsigned sV0 = sbase + QBUF + 2 * KVBUF;

    const int tid  = threadIdx.x;
    const int lane = tid & 31;
    const int warp = tid >> 5;               // 0..3
    const int g    = lane >> 2;
    const int cq   = lane & 3;
    const int wr   = warp * 32;              // warp's 32-row base

    const int b  = blockIdx.z;
    const int h  = blockIdx.y;
    const int q0 = blockIdx.x * 128;

    const __half* qb = qkv + (size_t)(b * Nx + q0) * TRI + h * DHx;
    const __half* kb = qkv + (size_t)b * Nx * TRI + INNER + h * DHx;
    const __half* vb = qkv + (size_t)b * Nx * TRI + 2 * INNER + h * DHx;

    auto stage_kv = [&](int slot, int kt) {
        #pragma unroll
        for (int i = 0; i < 4; i++) {
            int idx = tid + i * 128;         // 512 chunks of 16B each for K and V
            int row = idx >> 3;
            int j   = idx & 7;
            cp_async16(sK0 + slot * KVBUF + row * AROWB + j * 16,
                       kb + (size_t)(kt + row) * TRI + j * 8);
            cp_async16(sV0 + slot * KVBUF + row * AROWB + j * 16,
                       vb + (size_t)(kt + row) * TRI + j * 8);
        }
    };

    // Prologue: Q + first two K/V tiles
    {
        #pragma unroll
        for (int i = 0; i < 8; i++) {
            int idx = tid + i * 128;         // 1024 chunks
            int row = idx >> 3;
            int j   = idx & 7;
            cp_async16(sQ + row * AROWB + j * 16,
                       qb + (size_t)row * TRI + j * 8);
        }
        stage_kv(0, 0);
        cp_commit();
        stage_kv(1, 64);
        cp_commit();
    }

    cp_wait<1>();          // Q + KV tile0 complete
    __syncthreads();

    // ldmatrix lane-address components
    const int a_row = (lane & 7) + ((lane & 8) ? 8 : 0);
    const int a_col = (lane & 16) ? 16 : 0;
    const int b_row = (lane & 7) + ((lane & 16) ? 8 : 0);
    const int b_col = (lane & 8) ? 16 : 0;

    // Q fragment smem base addresses (fragments reloaded per tile)
    const unsigned qfa0 = sQ + (wr      + a_row) * AROWB + a_col;
    const unsigned qfa1 = sQ + (wr + 16 + a_row) * AROWB + a_col;

    constexpr unsigned ONES2 = 0x3C003C00u;  // fp16 (1.0, 1.0)

    float o[2][8][4] = {};
    float oL[2][4] = {};              // l accumulators (c[0]=row g, c[2]=row g+8)

    constexpr int NT = Nx / 64;       // 32 tiles
    for (int it = 0; it < NT; it++) {
        const int bf = it & 1;
        if (it + 2 < NT) cp_wait<1>(); else cp_wait<0>();
        __syncthreads();

        const unsigned sK = sK0 + bf * KVBUF;
        const unsigned sV = sV0 + bf * KVBUF;

        // S = Q @ K^T in fp16 accumulate (32 x 64 per warp)
        unsigned s[2][8][2] = {};     // fp16x2 accumulators == packed P layout
        #pragma unroll
        for (int kd = 0; kd < 4; kd++) {
            unsigned q0f[4], q1f[4], bk[4][4];
            ldsm4(q0f[0], q0f[1], q0f[2], q0f[3], qfa0 + kd * 32);
            ldsm4(q1f[0], q1f[1], q1f[2], q1f[3], qfa1 + kd * 32);
            #pragma unroll
            for (int p = 0; p < 4; p++)
                ldsm4(bk[p][0], bk[p][1], bk[p][2], bk[p][3],
                      sK + (p * 16 + b_row) * AROWB + kd * 32 + b_col);
            #pragma unroll
            for (int nt = 0; nt < 8; nt++) {
                mma_f16h(s[0][nt], q0f[0], q0f[1], q0f[2], q0f[3],
                         bk[nt >> 1][(nt & 1) * 2], bk[nt >> 1][(nt & 1) * 2 + 1]);
                mma_f16h(s[1][nt], q1f[0], q1f[1], q1f[2], q1f[3],
                         bk[nt >> 1][(nt & 1) * 2], bk[nt >> 1][(nt & 1) * 2 + 1]);
            }
        }

        // p = 2^s IN PLACE on the packed fp16x2 accumulators
        #pragma unroll
        for (int mt = 0; mt < 2; mt++)
            #pragma unroll
            for (int nt = 0; nt < 8; nt++) {
                s[mt][nt][0] = ex2_h2(s[mt][nt][0]);   // row g
                s[mt][nt][1] = ex2_h2(s[mt][nt][1]);   // row g+8
            }

        // O += P @ V; l += P @ ones (constant B fragment, no smem/ldsm)
        #pragma unroll
        for (int kc = 0; kc < 4; kc++) {
            unsigned bv[4][4];
            #pragma unroll
            for (int p = 0; p < 4; p++)
                ldsm4t(bv[p][0], bv[p][1], bv[p][2], bv[p][3],
                       sV + (kc * 16 + a_row) * AROWB + p * 32 + a_col);
            #pragma unroll
            for (int mt = 0; mt < 2; mt++) {
                unsigned pa0 = s[mt][2 * kc    ][0];
                unsigned pa1 = s[mt][2 * kc    ][1];
                unsigned pa2 = s[mt][2 * kc + 1][0];
                unsigned pa3 = s[mt][2 * kc + 1][1];
                #pragma unroll
                for (int nt = 0; nt < 8; nt++)
                    mma_f16(o[mt][nt], pa0, pa1, pa2, pa3,
                            bv[nt >> 1][(nt & 1) * 2], bv[nt >> 1][(nt & 1) * 2 + 1]);
                mma_f16(oL[mt], pa0, pa1, pa2, pa3, ONES2, ONES2);
            }
        }
        __syncthreads();
        if (it + 2 < NT) { stage_kv(bf, (it + 2) * 64); cp_commit(); }
    }

    // Epilogue: l fully reduced in oL (c[0]=row g, c[2]=row g+8)
    const size_t obase = (size_t)(b * Nx + q0) * INNER + h * DHx;
    #pragma unroll
    for (int mt = 0; mt < 2; mt++) {
        float inv0 = 1.0f / oL[mt][0];
        float inv1 = 1.0f / oL[mt][2];
        int row = wr + mt * 16;
        #pragma unroll
        for (int nt = 0; nt < 8; nt++) {
            int c = nt * 8 + 2 * cq;
            *(unsigned*)&outp[obase + (size_t)(row + g    ) * INNER + c] =
                pack2(o[mt][nt][0] * inv0, o[mt][nt][1] * inv0);
            *(unsigned*)&outp[obase + (size_t)(row + g + 8) * INNER + c] =
                pack2(o[mt][nt][2] * inv1, o[mt][nt][3] * inv1);
        }
    }
}

// ---------------------------------------------------------------------------
extern "C" void kernel_launch(void* const* d_in, const int* in_sizes, int n_in,
                              void* d_out, int out_size)
{
    const float* x     = (const float*)d_in[0];
    const float* w_qkv = (const float*)d_in[1];
    const float* b_qkv = (const float*)d_in[2];
    const float* w_out = (const float*)d_in[3];
    const float* b_out = (const float*)d_in[4];
    float* out = (float*)d_out;

    __half *qkvh, *atth, *xh, *wqh, *woh;
    cudaGetSymbolAddress((void**)&qkvh, g_qkvh);
    cudaGetSymbolAddress((void**)&atth, g_atth);
    cudaGetSymbolAddress((void**)&xh,  g_xh);
    cudaGetSymbolAddress((void**)&wqh, g_wqh);
    cudaGetSymbolAddress((void**)&woh, g_woh);

    cudaFuncSetAttribute(gemm_f16_kernel<2, 4>,
                         cudaFuncAttributeMaxDynamicSharedMemorySize, gemm_smem<2>());
    cudaFuncSetAttribute(attn_f16_kernel,
                         cudaFuncAttributeMaxDynamicSharedMemorySize, ATT_SMEM);

    // 0) fused fp32 -> fp16 conversion (x, w_qkv, w_out; layouts unchanged)
    {
        int n0 = MROWS * Dx / 4;       // 786432
        int n1 = Dx * TRI / 4;         // 442368
        int n2 = INNER * OUTD / 4;     // 147456
        int tot = n0 + n1 + n2;
        cvt3_kernel<<<(tot + 255) / 256, 256>>>(
            (const float4*)x,     (uint2*)xh,  n0,
            (const float4*)w_qkv, (uint2*)wqh, n1,
            (const float4*)w_out, (uint2*)woh, n2);
    }
    // 1) QKV projection: CTA 64x128, grid 1152 @ 4 CTAs/SM (~2 full waves)
    {
        dim3 grid(TRI / 128, MROWS / 64);
        gemm_f16_kernel<2, 4><<<grid, 128, gemm_smem<2>()>>>(
            xh, wqh, b_qkv, qkvh, Dx, TRI, 1);
    }
    // 2) Attention (fp16 out)
    {
        dim3 grid(Nx / 128, Hx, Bx);
        attn_f16_kernel<<<grid, 128, ATT_SMEM>>>(qkvh, atth);
    }
    // 3) Output projection (fp32 out): CTA 64x128, grid 384
    {
        dim3 grid(OUTD / 128, MROWS / 64);
        gemm_f16_kernel<2, 4><<<grid, 128, gemm_smem<2>()>>>(
            atth, woh, b_out, out, INNER, OUTD, 0);
    }
}